// round 3
// baseline (speedup 1.0000x reference)
#include <cuda_runtime.h>

#define M_ROWS   2048
#define NDIM     128
#define NN       (NDIM * NDIM)       // 16384 complex entries of matH
#define NV4      (NN / 4)            // 4096 float4 per row per component
#define HV4      (NV4 / 2)           // 2048 float4 per column-half
#define HNN      (NN / 2)            // 8192 floats of h per half (per component)
#define UNITS    16                  // 128-float4 units per half-row
#define NUNIT    (M_ROWS * UNITS)    // 32768 units per parity
#define THREADS  512

// Device scratch (allocation-free rule: __device__ globals)
__device__ float    g_pr[2 * NUNIT];     // per-(parity,row,unit) partial Re
__device__ float    g_pi[2 * NUNIT];     // per-(parity,row,unit) partial Im
__device__ unsigned g_ctr = 0;

// ---------------------------------------------------------------------------
// Fused kernel, 3 blocks/SM:
//  phase A: block builds ITS column-half of matH (64 KB smem), parity = bid&1
//  phase B: warp-per-2KB-unit streaming dots (256 MB read once), balanced
//  phase C: last-arriving block does the deterministic final reduction
// ---------------------------------------------------------------------------
__global__ __launch_bounds__(THREADS, 3) void fused_kernel(
    const float* __restrict__ bre, const float* __restrict__ bim,
    const float* __restrict__ theta, const float* __restrict__ evl,
    float* __restrict__ out)
{
    extern __shared__ float sh[];             // 2 * HNN floats = 64 KB
    float* hre = sh;                          // this block's half of Re(h)
    float* him = sh + HNN;

    __shared__ float e0r[NDIM], e0i[NDIM], e1r[NDIM], e1i[NDIM];
    __shared__ float wred[THREADS / 32];
    __shared__ float sc[6];
    __shared__ unsigned slast;

    const int tid  = threadIdx.x;
    const int lane = tid & 31;
    const int warp = tid >> 5;
    const int p    = blockIdx.x & 1;          // column-half parity
    const int pb   = blockIdx.x >> 1;         // block index within parity
    const int nblk = gridDim.x >> 1;          // blocks per parity (grid even)

    // ---------------- phase A: eigvectors + this half of matH ----------------
    float th0 = 0.f, th1 = 0.f, th2 = 0.f, th3 = 0.f;
    if (tid < NDIM) {
        th0 = theta[tid];
        th1 = theta[NDIM + tid];
        th2 = theta[2 * NDIM + tid];
        th3 = theta[3 * NDIM + tid];
    }

    auto blockReduce = [&](float v, int slot) -> float {
        #pragma unroll
        for (int o = 16; o; o >>= 1) v += __shfl_xor_sync(0xffffffffu, v, o);
        if (lane == 0) wred[warp] = v;
        __syncthreads();
        if (tid == 0) {
            float s = 0.f;
            #pragma unroll
            for (int i = 0; i < THREADS / 32; i++) s += wred[i];
            sc[slot] = s;
        }
        __syncthreads();
        return sc[slot];
    };

    const float s0   = blockReduce(th0 * th0 + th1 * th1, 0);
    const float inv0 = rsqrtf(s0);
    const float a0 = th0 * inv0, b0 = th1 * inv0;           // evc0
    const float dr = blockReduce(a0 * th2 + b0 * th3, 1);   // Re vdot(evc0,c1)
    const float di = blockReduce(a0 * th3 - b0 * th2, 2);   // Im vdot(evc0,c1)
    const float c1r = th2 - (dr * a0 - di * b0);
    const float c1i = th3 - (dr * b0 + di * a0);
    const float s1   = blockReduce(c1r * c1r + c1i * c1i, 3);
    const float inv1 = rsqrtf(s1);

    if (tid < NDIM) {
        e0r[tid] = a0;         e0i[tid] = b0;
        e1r[tid] = c1r * inv1; e1i[tid] = c1i * inv1;
    }
    if (tid == 0) {
        const float l0 = log1pf(expf(evl[0]));
        const float l1 = log1pf(expf(evl[1]));
        const float nl = rsqrtf(l0 * l0 + l1 * l1);
        sc[4] = l0 * nl;                                     // lam0
        sc[5] = l1 * nl;                                     // lam1
    }
    __syncthreads();
    const float lam0 = sc[4], lam1 = sc[5];

    // build columns [p*HNN, (p+1)*HNN) of flattened h, stored locally
    #pragma unroll
    for (int k = 0; k < HNN / THREADS; k++) {
        const int cl = tid + k * THREADS;                    // local flat index
        const int cg = p * HNN + cl;                         // global flat index
        const int i = cg >> 7, j = cg & (NDIM - 1);
        const float A0 = e0r[i], B0 = e0i[i], A1 = e1r[i], B1 = e1i[i];
        const float aj0 = e0r[j], bj0 = e0i[j], aj1 = e1r[j], bj1 = e1i[j];
        hre[cl] = lam0 * (A0 * aj0 + B0 * bj0) - lam1 * (A1 * aj1 + B1 * bj1);
        him[cl] = lam0 * (B0 * aj0 - A0 * bj0) - lam1 * (B1 * aj1 - A1 * bj1);
    }
    __syncthreads();

    // ---------------- phase B: balanced 2KB-unit streaming dots ----------------
    // v = (re - i*im) . (hre + i*him):
    //   vr += re*hre + im*him ;  vi += re*him - im*hre
    const float4* hre4 = (const float4*)hre;
    const float4* him4 = (const float4*)him;
    const int nslots = (THREADS / 32) * nblk;                // warps per parity
    const int ws = warp * nblk + pb;

    for (int t = ws; t < NUNIT; t += nslots) {
        const int row = t >> 4;                              // 0..2047
        const int u   = t & (UNITS - 1);                     // 0..15
        const int hb  = u * 128 + lane;                      // local h float4 idx
        const float4* br = (const float4*)bre
                         + (size_t)row * NV4 + p * HV4 + u * 128 + lane;
        const float4* bi = (const float4*)bim
                         + (size_t)row * NV4 + p * HV4 + u * 128 + lane;

        float vr = 0.f, vi = 0.f;
        // batch 1: 4 in-flight float4 loads
        {
            const float4 r0 = __ldcs(br);
            const float4 r1 = __ldcs(br + 32);
            const float4 m0 = __ldcs(bi);
            const float4 m1 = __ldcs(bi + 32);
            float4 h, g;
            h = hre4[hb];      g = him4[hb];
            vr += r0.x*h.x + m0.x*g.x;  vi += r0.x*g.x - m0.x*h.x;
            vr += r0.y*h.y + m0.y*g.y;  vi += r0.y*g.y - m0.y*h.y;
            vr += r0.z*h.z + m0.z*g.z;  vi += r0.z*g.z - m0.z*h.z;
            vr += r0.w*h.w + m0.w*g.w;  vi += r0.w*g.w - m0.w*h.w;
            h = hre4[hb + 32]; g = him4[hb + 32];
            vr += r1.x*h.x + m1.x*g.x;  vi += r1.x*g.x - m1.x*h.x;
            vr += r1.y*h.y + m1.y*g.y;  vi += r1.y*g.y - m1.y*h.y;
            vr += r1.z*h.z + m1.z*g.z;  vi += r1.z*g.z - m1.z*h.z;
            vr += r1.w*h.w + m1.w*g.w;  vi += r1.w*g.w - m1.w*h.w;
        }
        // batch 2
        {
            const float4 r2 = __ldcs(br + 64);
            const float4 r3 = __ldcs(br + 96);
            const float4 m2 = __ldcs(bi + 64);
            const float4 m3 = __ldcs(bi + 96);
            float4 h, g;
            h = hre4[hb + 64]; g = him4[hb + 64];
            vr += r2.x*h.x + m2.x*g.x;  vi += r2.x*g.x - m2.x*h.x;
            vr += r2.y*h.y + m2.y*g.y;  vi += r2.y*g.y - m2.y*h.y;
            vr += r2.z*h.z + m2.z*g.z;  vi += r2.z*g.z - m2.z*h.z;
            vr += r2.w*h.w + m2.w*g.w;  vi += r2.w*g.w - m2.w*h.w;
            h = hre4[hb + 96]; g = him4[hb + 96];
            vr += r3.x*h.x + m3.x*g.x;  vi += r3.x*g.x - m3.x*h.x;
            vr += r3.y*h.y + m3.y*g.y;  vi += r3.y*g.y - m3.y*h.y;
            vr += r3.z*h.z + m3.z*g.z;  vi += r3.z*g.z - m3.z*h.z;
            vr += r3.w*h.w + m3.w*g.w;  vi += r3.w*g.w - m3.w*h.w;
        }
        #pragma unroll
        for (int o = 16; o; o >>= 1) {
            vr += __shfl_xor_sync(0xffffffffu, vr, o);
            vi += __shfl_xor_sync(0xffffffffu, vi, o);
        }
        if (lane == 0) {
            g_pr[p * NUNIT + t] = vr;
            g_pi[p * NUNIT + t] = vi;
        }
    }

    // ---------------- phase C: last block reduces ----------------
    __syncthreads();
    if (tid == 0) {
        __threadfence();
        const unsigned old = atomicAdd(&g_ctr, 1u);
        slast = (old == gridDim.x - 1) ? 1u : 0u;
        if (slast) g_ctr = 0;                                // reset for replay
    }
    __syncthreads();

    if (slast) {
        float acc = 0.f;
        for (int r = tid; r < M_ROWS; r += THREADS) {        // 4 rows per thread
            const float4* p0r = (const float4*)&g_pr[r * UNITS];
            const float4* p0i = (const float4*)&g_pi[r * UNITS];
            const float4* p1r = (const float4*)&g_pr[NUNIT + r * UNITS];
            const float4* p1i = (const float4*)&g_pi[NUNIT + r * UNITS];
            float vr = 0.f, vi = 0.f;
            #pragma unroll
            for (int k = 0; k < UNITS / 4; k++) {
                const float4 a = __ldcg(p0r + k);
                const float4 b = __ldcg(p1r + k);
                vr += (a.x + a.y + a.z + a.w) + (b.x + b.y + b.z + b.w);
                const float4 c = __ldcg(p0i + k);
                const float4 d = __ldcg(p1i + k);
                vi += (c.x + c.y + c.z + c.w) + (d.x + d.y + d.z + d.w);
            }
            acc += vr * vr + vi * vi;
        }
        #pragma unroll
        for (int o = 16; o; o >>= 1) acc += __shfl_xor_sync(0xffffffffu, acc, o);
        if (lane == 0) wred[warp] = acc;
        __syncthreads();
        if (warp == 0) {
            float v = (lane < THREADS / 32) ? wred[lane] : 0.f;
            #pragma unroll
            for (int o = 8; o; o >>= 1) v += __shfl_xor_sync(0xffffffffu, v, o);
            if (lane == 0) out[0] = v;
        }
    }
}

// ---------------------------------------------------------------------------
extern "C" void kernel_launch(void* const* d_in, const int* in_sizes, int n_in,
                              void* d_out, int out_size) {
    const float* bre   = (const float*)d_in[0];
    const float* bim   = (const float*)d_in[1];
    const float* theta = (const float*)d_in[2];
    const float* evl   = (const float*)d_in[3];

    int sms = 148;
    cudaDeviceGetAttribute(&sms, cudaDevAttrMultiProcessorCount, 0);

    int grid = 3 * sms;
    if (grid & 1) grid++;                                    // parity needs even

    const int smem = 2 * HNN * (int)sizeof(float);           // 64 KB
    cudaFuncSetAttribute(fused_kernel, cudaFuncAttributeMaxDynamicSharedMemorySize, smem);

    fused_kernel<<<grid, THREADS, smem>>>(bre, bim, theta, evl, (float*)d_out);
}

// round 4
// speedup vs baseline: 1.4725x; 1.4725x over previous
#include <cuda_runtime.h>

#define M_ROWS   2048
#define NDIM     128
#define NN       (NDIM * NDIM)       // 16384 complex entries of matH
#define NV4      (NN / 4)            // 4096 float4 per row per component
#define QV4      (NV4 / 4)           // 1024 float4 per quarter-row
#define NTASKS   (4 * M_ROWS)        // 8192 quarter-row tasks
#define THREADS  1024

// Device scratch (allocation-free rule: __device__ globals)
__device__ float    g_pr[NTASKS];    // per-quarter-row partial Re
__device__ float    g_pi[NTASKS];    // per-quarter-row partial Im
__device__ unsigned g_task = 0;      // dynamic work counter
__device__ unsigned g_ctr  = 0;      // block-arrival counter

// ---------------------------------------------------------------------------
// One fused persistent kernel, 1 block/SM, 128 KB smem:
//  phase A: every block redundantly builds the FULL matH in its smem
//  phase B: warps dynamically grab quarter-row tasks (8-iter streaming loop)
//  phase C: last-arriving block does the deterministic final reduction
// ---------------------------------------------------------------------------
__global__ __launch_bounds__(THREADS, 1) void fused_kernel(
    const float* __restrict__ bre, const float* __restrict__ bim,
    const float* __restrict__ theta, const float* __restrict__ evl,
    float* __restrict__ out)
{
    extern __shared__ float sh[];             // 2 * NN floats = 128 KB
    float* hre = sh;
    float* him = sh + NN;

    __shared__ float e0r[NDIM], e0i[NDIM], e1r[NDIM], e1i[NDIM];
    __shared__ float wred[THREADS / 32];
    __shared__ float sc[6];
    __shared__ unsigned slast;

    const int tid  = threadIdx.x;
    const int lane = tid & 31;
    const int warp = tid >> 5;

    // ---------------- phase A: eigvectors + matH ----------------
    float th0 = 0.f, th1 = 0.f, th2 = 0.f, th3 = 0.f;
    if (tid < NDIM) {
        th0 = theta[tid];
        th1 = theta[NDIM + tid];
        th2 = theta[2 * NDIM + tid];
        th3 = theta[3 * NDIM + tid];
    }

    auto blockReduce = [&](float v, int slot) -> float {
        #pragma unroll
        for (int o = 16; o; o >>= 1) v += __shfl_xor_sync(0xffffffffu, v, o);
        if (lane == 0) wred[warp] = v;
        __syncthreads();
        if (tid == 0) {
            float s = 0.f;
            #pragma unroll
            for (int i = 0; i < THREADS / 32; i++) s += wred[i];
            sc[slot] = s;
        }
        __syncthreads();
        return sc[slot];
    };

    const float s0   = blockReduce(th0 * th0 + th1 * th1, 0);
    const float inv0 = rsqrtf(s0);
    const float a0 = th0 * inv0, b0 = th1 * inv0;           // evc0
    const float dr = blockReduce(a0 * th2 + b0 * th3, 1);   // Re vdot(evc0,c1)
    const float di = blockReduce(a0 * th3 - b0 * th2, 2);   // Im vdot(evc0,c1)
    const float c1r = th2 - (dr * a0 - di * b0);
    const float c1i = th3 - (dr * b0 + di * a0);
    const float s1   = blockReduce(c1r * c1r + c1i * c1i, 3);
    const float inv1 = rsqrtf(s1);

    if (tid < NDIM) {
        e0r[tid] = a0;         e0i[tid] = b0;
        e1r[tid] = c1r * inv1; e1i[tid] = c1i * inv1;
    }
    if (tid == 0) {
        const float l0 = log1pf(expf(evl[0]));
        const float l1 = log1pf(expf(evl[1]));
        const float nl = rsqrtf(l0 * l0 + l1 * l1);
        sc[4] = l0 * nl;                                     // lam0
        sc[5] = l1 * nl;                                     // lam1
    }
    __syncthreads();
    const float lam0 = sc[4], lam1 = sc[5];

    #pragma unroll
    for (int k = 0; k < NN / THREADS; k++) {
        const int c = tid + k * THREADS;                     // stride-1 writes
        const int i = c >> 7, j = c & (NDIM - 1);
        const float A0 = e0r[i], B0 = e0i[i], A1 = e1r[i], B1 = e1i[i];
        const float aj0 = e0r[j], bj0 = e0i[j], aj1 = e1r[j], bj1 = e1i[j];
        hre[c] = lam0 * (A0 * aj0 + B0 * bj0) - lam1 * (A1 * aj1 + B1 * bj1);
        him[c] = lam0 * (B0 * aj0 - A0 * bj0) - lam1 * (B1 * aj1 - A1 * bj1);
    }
    __syncthreads();

    // ---------------- phase B: work-stolen quarter-row streaming ----------------
    // v = (re - i*im) . (hre + i*him):
    //   vr += re*hre + im*him ;  vi += re*him - im*hre
    const float4* hre4 = (const float4*)hre;
    const float4* him4 = (const float4*)him;

    for (;;) {
        unsigned t;
        if (lane == 0) t = atomicAdd(&g_task, 1u);
        t = __shfl_sync(0xffffffffu, t, 0);
        if (t >= NTASKS) break;

        const int row = t >> 2;                              // 0..2047
        const int q   = t & 3;                               // quarter index
        const int hb  = q * QV4 + lane;                      // h float4 base
        const float4* br = (const float4*)bre + (size_t)row * NV4 + q * QV4 + lane;
        const float4* bi = (const float4*)bim + (size_t)row * NV4 + q * QV4 + lane;

        float vr = 0.f, vi = 0.f;
        #pragma unroll 1
        for (int it = 0; it < 8; it++) {                     // 8 x 128 float4
            const int c = it * 128;
            const float4 r0 = __ldcs(br + c);
            const float4 r1 = __ldcs(br + c + 32);
            const float4 r2 = __ldcs(br + c + 64);
            const float4 r3 = __ldcs(br + c + 96);
            const float4 m0 = __ldcs(bi + c);
            const float4 m1 = __ldcs(bi + c + 32);
            const float4 m2 = __ldcs(bi + c + 64);
            const float4 m3 = __ldcs(bi + c + 96);

            float4 h, g;
            h = hre4[hb + c];      g = him4[hb + c];
            vr += r0.x*h.x + m0.x*g.x;  vi += r0.x*g.x - m0.x*h.x;
            vr += r0.y*h.y + m0.y*g.y;  vi += r0.y*g.y - m0.y*h.y;
            vr += r0.z*h.z + m0.z*g.z;  vi += r0.z*g.z - m0.z*h.z;
            vr += r0.w*h.w + m0.w*g.w;  vi += r0.w*g.w - m0.w*h.w;
            h = hre4[hb + c + 32]; g = him4[hb + c + 32];
            vr += r1.x*h.x + m1.x*g.x;  vi += r1.x*g.x - m1.x*h.x;
            vr += r1.y*h.y + m1.y*g.y;  vi += r1.y*g.y - m1.y*h.y;
            vr += r1.z*h.z + m1.z*g.z;  vi += r1.z*g.z - m1.z*h.z;
            vr += r1.w*h.w + m1.w*g.w;  vi += r1.w*g.w - m1.w*h.w;
            h = hre4[hb + c + 64]; g = him4[hb + c + 64];
            vr += r2.x*h.x + m2.x*g.x;  vi += r2.x*g.x - m2.x*h.x;
            vr += r2.y*h.y + m2.y*g.y;  vi += r2.y*g.y - m2.y*h.y;
            vr += r2.z*h.z + m2.z*g.z;  vi += r2.z*g.z - m2.z*h.z;
            vr += r2.w*h.w + m2.w*g.w;  vi += r2.w*g.w - m2.w*h.w;
            h = hre4[hb + c + 96]; g = him4[hb + c + 96];
            vr += r3.x*h.x + m3.x*g.x;  vi += r3.x*g.x - m3.x*h.x;
            vr += r3.y*h.y + m3.y*g.y;  vi += r3.y*g.y - m3.y*h.y;
            vr += r3.z*h.z + m3.z*g.z;  vi += r3.z*g.z - m3.z*h.z;
            vr += r3.w*h.w + m3.w*g.w;  vi += r3.w*g.w - m3.w*h.w;
        }
        #pragma unroll
        for (int o = 16; o; o >>= 1) {
            vr += __shfl_xor_sync(0xffffffffu, vr, o);
            vi += __shfl_xor_sync(0xffffffffu, vi, o);
        }
        if (lane == 0) { g_pr[t] = vr; g_pi[t] = vi; }
    }

    // ---------------- phase C: last block reduces ----------------
    __syncthreads();
    if (tid == 0) {
        __threadfence();
        const unsigned old = atomicAdd(&g_ctr, 1u);
        slast = (old == gridDim.x - 1) ? 1u : 0u;
        if (slast) { g_ctr = 0; g_task = 0; }                // reset for replay
    }
    __syncthreads();

    if (slast) {
        float acc = 0.f;
        for (int r = tid; r < M_ROWS; r += THREADS) {        // 2 rows per thread
            const float4 a = __ldcg((const float4*)&g_pr[r * 4]);
            const float4 b = __ldcg((const float4*)&g_pi[r * 4]);
            const float vr = a.x + a.y + a.z + a.w;
            const float vi = b.x + b.y + b.z + b.w;
            acc += vr * vr + vi * vi;
        }
        #pragma unroll
        for (int o = 16; o; o >>= 1) acc += __shfl_xor_sync(0xffffffffu, acc, o);
        if (lane == 0) wred[warp] = acc;
        __syncthreads();
        if (warp == 0) {
            float v = wred[lane];
            #pragma unroll
            for (int o = 16; o; o >>= 1) v += __shfl_xor_sync(0xffffffffu, v, o);
            if (lane == 0) out[0] = v;
        }
    }
}

// ---------------------------------------------------------------------------
extern "C" void kernel_launch(void* const* d_in, const int* in_sizes, int n_in,
                              void* d_out, int out_size) {
    const float* bre   = (const float*)d_in[0];
    const float* bim   = (const float*)d_in[1];
    const float* theta = (const float*)d_in[2];
    const float* evl   = (const float*)d_in[3];

    int sms = 148;
    cudaDeviceGetAttribute(&sms, cudaDevAttrMultiProcessorCount, 0);

    const int smem = 2 * NN * (int)sizeof(float);            // 128 KB
    cudaFuncSetAttribute(fused_kernel, cudaFuncAttributeMaxDynamicSharedMemorySize, smem);

    fused_kernel<<<sms, THREADS, smem>>>(bre, bim, theta, evl, (float*)d_out);
}